// round 4
// baseline (speedup 1.0000x reference)
#include <cuda_runtime.h>
#include <cstdint>

#define BATCH  64
#define HID    1024
#define VOCAB  4096
#define SEQ    256

// Scratch (static device allocation is allowed; cudaMalloc is not).
// g_H[t] = hidden state BEFORE step t; g_H[t+1] written by step t. g_H[0] zeroed each call.
__device__ float g_H[(SEQ + 1) * BATCH * HID];   // ~67 MB
__device__ float g_z[BATCH * HID];               // z gate
__device__ float g_P[BATCH * HID];               // r * H  (input to h-gate GEMM)

// ---------------------------------------------------------------------------
// helpers
// ---------------------------------------------------------------------------
__device__ __forceinline__ float tf32r(float x) {
    unsigned u;
    asm("cvt.rna.tf32.f32 %0, %1;" : "=r"(u) : "f"(x));
    return __uint_as_float(u);
}

__device__ __forceinline__ void mma8(float (&c)[4], const float (&a)[4], float b0, float b1) {
    unsigned a0 = __float_as_uint(a[0]), a1 = __float_as_uint(a[1]);
    unsigned a2 = __float_as_uint(a[2]), a3 = __float_as_uint(a[3]);
    unsigned B0 = __float_as_uint(b0),  B1 = __float_as_uint(b1);
    asm volatile(
        "mma.sync.aligned.m16n8k8.row.col.f32.tf32.tf32.f32 "
        "{%0,%1,%2,%3}, {%4,%5,%6,%7}, {%8,%9}, {%0,%1,%2,%3};\n"
        : "+f"(c[0]), "+f"(c[1]), "+f"(c[2]), "+f"(c[3])
        : "r"(a0), "r"(a1), "r"(a2), "r"(a3), "r"(B0), "r"(B1));
}

// ---------------------------------------------------------------------------
// GEMM core:  C[64 x (NI*16)] += A[64 x 1024] * B[1024 x (NI*16)]
//   A: row-major, lda = 1024 (HID)
//   B: split into two halves of NI*8 columns: B0 (cols 0..NI*8-1), B1 (rest),
//      both row-major with leading dim ldb. (Lets one block serve two weight
//      matrices for the z|r fused kernel.)
//   128 threads = 4 warps in 2(m) x 2(n); warp tile = 32 x (NI*8).
//   tf32 rounding applied when staging to smem; double-buffered via registers.
// ---------------------------------------------------------------------------
template<int NI>
__device__ __forceinline__ void gemm_core(
    const float* __restrict__ A,
    const float* __restrict__ B0,
    const float* __restrict__ B1,
    int ldb,
    float (&acc)[2][NI][4],
    float* As,   // [64][36]
    float* Bs)   // [32][NI*16 + 8]
{
    constexpr int BN   = NI * 16;
    constexpr int BSTR = BN + 8;

    const int tid  = threadIdx.x;
    const int lane = tid & 31;
    const int w    = tid >> 5;
    const int wm   = w >> 1;
    const int wn   = w & 1;
    const int gid  = lane >> 2;   // groupID
    const int tg   = lane & 3;    // threadID_in_group

#pragma unroll
    for (int mi = 0; mi < 2; ++mi)
#pragma unroll
        for (int ni = 0; ni < NI; ++ni)
#pragma unroll
            for (int e = 0; e < 4; ++e) acc[mi][ni][e] = 0.f;

    float4 ra[4];
    float4 rb[NI];

    // prologue: prefetch K-tile 0
#pragma unroll
    for (int j = 0; j < 4; ++j) {
        int i = tid + j * 128;
        int row = i >> 3, kq = i & 7;
        ra[j] = *reinterpret_cast<const float4*>(A + (size_t)row * HID + kq * 4);
    }
#pragma unroll
    for (int j = 0; j < NI; ++j) {
        int i = tid + j * 128;
        int row = i / (BN / 4), nq = i % (BN / 4);
        int c4 = nq * 4;
        const float* src = (c4 < NI * 8) ? (B0 + (size_t)row * ldb + c4)
                                         : (B1 + (size_t)row * ldb + (c4 - NI * 8));
        rb[j] = *reinterpret_cast<const float4*>(src);
    }

    for (int kk = 0; kk < HID; kk += 32) {
        // stage registers -> smem with tf32 rounding
#pragma unroll
        for (int j = 0; j < 4; ++j) {
            int i = tid + j * 128;
            int row = i >> 3, kq = i & 7;
            float4 v;
            v.x = tf32r(ra[j].x); v.y = tf32r(ra[j].y);
            v.z = tf32r(ra[j].z); v.w = tf32r(ra[j].w);
            *reinterpret_cast<float4*>(As + row * 36 + kq * 4) = v;
        }
#pragma unroll
        for (int j = 0; j < NI; ++j) {
            int i = tid + j * 128;
            int row = i / (BN / 4), nq = i % (BN / 4);
            float4 v;
            v.x = tf32r(rb[j].x); v.y = tf32r(rb[j].y);
            v.z = tf32r(rb[j].z); v.w = tf32r(rb[j].w);
            *reinterpret_cast<float4*>(Bs + row * BSTR + nq * 4) = v;
        }
        __syncthreads();

        // prefetch next K-tile (overlaps with compute below)
        if (kk + 32 < HID) {
#pragma unroll
            for (int j = 0; j < 4; ++j) {
                int i = tid + j * 128;
                int row = i >> 3, kq = i & 7;
                ra[j] = *reinterpret_cast<const float4*>(A + (size_t)row * HID + kk + 32 + kq * 4);
            }
#pragma unroll
            for (int j = 0; j < NI; ++j) {
                int i = tid + j * 128;
                int row = i / (BN / 4), nq = i % (BN / 4);
                int c4 = nq * 4;
                const float* src = (c4 < NI * 8)
                    ? (B0 + (size_t)(kk + 32 + row) * ldb + c4)
                    : (B1 + (size_t)(kk + 32 + row) * ldb + (c4 - NI * 8));
                rb[j] = *reinterpret_cast<const float4*>(src);
            }
        }

        // compute 4 k8-steps
#pragma unroll
        for (int k8 = 0; k8 < 4; ++k8) {
            int kb = k8 * 8;
            float a[2][4];
#pragma unroll
            for (int mi = 0; mi < 2; ++mi) {
                int rb0 = wm * 32 + mi * 16;
                a[mi][0] = As[(rb0 + gid) * 36 + kb + tg];
                a[mi][1] = As[(rb0 + 8 + gid) * 36 + kb + tg];
                a[mi][2] = As[(rb0 + gid) * 36 + kb + 4 + tg];
                a[mi][3] = As[(rb0 + 8 + gid) * 36 + kb + 4 + tg];
            }
#pragma unroll
            for (int ni = 0; ni < NI; ++ni) {
                int col = wn * (NI * 8) + ni * 8 + gid;
                float b0 = Bs[(kb + tg) * BSTR + col];
                float b1 = Bs[(kb + 4 + tg) * BSTR + col];
#pragma unroll
                for (int mi = 0; mi < 2; ++mi) mma8(acc[mi][ni], a[mi], b0, b1);
            }
        }
        __syncthreads();
    }
}

__device__ __forceinline__ float sigmoidf_(float x) {
    return 1.f / (1.f + __expf(-x));
}

// ---------------------------------------------------------------------------
// Kernel 1 (per step): z and r gates fused. grid = 64 blocks.
//   Block covers cols [n0, n0+16) of BOTH Wz_h (z) and Wr_h (r), sharing the
//   H tile. Epilogue: z -> g_z ; r -> g_P = r * H.
// ---------------------------------------------------------------------------
__global__ void __launch_bounds__(128)
gru_gates(const float* __restrict__ Wz, const float* __restrict__ bz,
          const float* __restrict__ Wr, const float* __restrict__ br,
          const int* __restrict__ X, int t)
{
    __shared__ float As[64 * 36];
    __shared__ float Bs[32 * 40];

    const int n0 = blockIdx.x * 16;
    const float* Hc = g_H + (size_t)t * (BATCH * HID);
    const float* B0 = Wz + (size_t)VOCAB * HID + n0;   // z-gate recurrent weights
    const float* B1 = Wr + (size_t)VOCAB * HID + n0;   // r-gate recurrent weights

    float acc[2][2][4];
    gemm_core<2>(Hc, B0, B1, HID, acc, As, Bs);

    const int lane = threadIdx.x & 31;
    const int w    = threadIdx.x >> 5;
    const int wm = w >> 1, wn = w & 1;
    const int gid = lane >> 2, tg = lane & 3;

#pragma unroll
    for (int mi = 0; mi < 2; ++mi) {
#pragma unroll
        for (int half = 0; half < 2; ++half) {
            int row = wm * 32 + mi * 16 + half * 8 + gid;   // batch index
            int xb = X[row * SEQ + t];
#pragma unroll
            for (int ni = 0; ni < 2; ++ni) {
#pragma unroll
                for (int e = 0; e < 2; ++e) {
                    int c = wn * 16 + ni * 8 + tg * 2 + e;
                    float v = acc[mi][ni][half * 2 + e];
                    bool isr = (c >= 16);
                    int n = n0 + (isr ? c - 16 : c);
                    const float* W  = isr ? Wr : Wz;
                    const float* bb = isr ? br : bz;
                    float pre = v + W[(size_t)xb * HID + n] + bb[n];
                    float s = sigmoidf_(pre);
                    int idx = row * HID + n;
                    if (isr) g_P[idx] = s * Hc[idx];
                    else     g_z[idx] = s;
                }
            }
        }
    }
}

// ---------------------------------------------------------------------------
// Kernel 2 (per step): h gate + state update. grid = 32 blocks.
//   Ah = (r*H) @ Wh_h ; h = tanh(Ah + Wh_x[x] + bh) ; H' = z*h + (1-z)*H
// ---------------------------------------------------------------------------
__global__ void __launch_bounds__(128)
gru_hupd(const float* __restrict__ Wh, const float* __restrict__ bh,
         const int* __restrict__ X, int t)
{
    __shared__ float As[64 * 36];
    __shared__ float Bs[32 * 40];

    const int n0 = blockIdx.x * 32;
    const float* Hc = g_H + (size_t)t * (BATCH * HID);
    float* Hn = g_H + (size_t)(t + 1) * (BATCH * HID);
    const float* B0 = Wh + (size_t)VOCAB * HID + n0;
    const float* B1 = B0 + 16;

    float acc[2][2][4];
    gemm_core<2>(g_P, B0, B1, HID, acc, As, Bs);

    const int lane = threadIdx.x & 31;
    const int w    = threadIdx.x >> 5;
    const int wm = w >> 1, wn = w & 1;
    const int gid = lane >> 2, tg = lane & 3;

#pragma unroll
    for (int mi = 0; mi < 2; ++mi) {
#pragma unroll
        for (int half = 0; half < 2; ++half) {
            int row = wm * 32 + mi * 16 + half * 8 + gid;
            int xb = X[row * SEQ + t];
#pragma unroll
            for (int ni = 0; ni < 2; ++ni) {
#pragma unroll
                for (int e = 0; e < 2; ++e) {
                    int c = wn * 16 + ni * 8 + tg * 2 + e;
                    int n = n0 + c;
                    float v = acc[mi][ni][half * 2 + e];
                    float pre = v + Wh[(size_t)xb * HID + n] + bh[n];
                    float hh = tanhf(pre);
                    int idx = row * HID + n;
                    float z = g_z[idx];
                    Hn[idx] = z * hh + (1.f - z) * Hc[idx];
                }
            }
        }
    }
}

// ---------------------------------------------------------------------------
// Kernel 3 (once): Y = H_all[16384 x 1024] @ Wo[1024 x 4096] + bo
//   grid = (64 n-tiles, 256 m-tiles), NI=4 core (64x64 block tile).
// ---------------------------------------------------------------------------
__global__ void __launch_bounds__(128)
gru_out(const float* __restrict__ Wo, const float* __restrict__ bo,
        float* __restrict__ out)
{
    __shared__ float As[64 * 36];
    __shared__ float Bs[32 * 72];

    const int n0 = blockIdx.x * 64;
    const int m0 = blockIdx.y * 64;
    const float* A = g_H + (size_t)(BATCH * HID) + (size_t)m0 * HID; // H after step t; row = t*64+b
    const float* B0 = Wo + n0;
    const float* B1 = Wo + n0 + 32;

    float acc[2][4][4];
    gemm_core<4>(A, B0, B1, VOCAB, acc, As, Bs);

    const int lane = threadIdx.x & 31;
    const int w    = threadIdx.x >> 5;
    const int wm = w >> 1, wn = w & 1;
    const int gid = lane >> 2, tg = lane & 3;

#pragma unroll
    for (int mi = 0; mi < 2; ++mi) {
#pragma unroll
        for (int half = 0; half < 2; ++half) {
            int row = m0 + wm * 32 + mi * 16 + half * 8 + gid;
#pragma unroll
            for (int ni = 0; ni < 4; ++ni) {
#pragma unroll
                for (int e = 0; e < 2; ++e) {
                    int c = wn * 32 + ni * 8 + tg * 2 + e;
                    int n = n0 + c;
                    out[(size_t)row * VOCAB + n] = acc[mi][ni][half * 2 + e] + bo[n];
                }
            }
        }
    }
}

// ---------------------------------------------------------------------------
// small utility kernels
// ---------------------------------------------------------------------------
__global__ void gru_zero_h0() {
    int i = blockIdx.x * blockDim.x + threadIdx.x;
    if (i < BATCH * HID) g_H[i] = 0.f;
}

__global__ void gru_copy_hfinal(float* __restrict__ dst) {
    int i = blockIdx.x * blockDim.x + threadIdx.x;
    if (i < BATCH * HID) dst[i] = g_H[(size_t)SEQ * (BATCH * HID) + i];
}

// ---------------------------------------------------------------------------
extern "C" void kernel_launch(void* const* d_in, const int* in_sizes, int n_in,
                              void* d_out, int out_size)
{
    const int*   X  = (const int*)  d_in[0];
    const float* Wz = (const float*)d_in[1];
    const float* bz = (const float*)d_in[2];
    const float* Wr = (const float*)d_in[3];
    const float* br = (const float*)d_in[4];
    const float* Wh = (const float*)d_in[5];
    const float* bh = (const float*)d_in[6];
    const float* Wo = (const float*)d_in[7];
    const float* bo = (const float*)d_in[8];
    float* out = (float*)d_out;

    gru_zero_h0<<<64, 1024>>>();

    for (int t = 0; t < SEQ; ++t) {
        gru_gates<<<64, 128>>>(Wz, bz, Wr, br, X, t);
        gru_hupd<<<32, 128>>>(Wh, bh, X, t);
    }

    gru_out<<<dim3(VOCAB / 64, (SEQ * BATCH) / 64), 128>>>(Wo, bo, out);

    // If the harness also checks H_final appended after Y, provide it.
    const long long ybytes = (long long)SEQ * BATCH * VOCAB;
    if ((long long)out_size >= ybytes + (long long)BATCH * HID) {
        gru_copy_hfinal<<<64, 1024>>>(out + ybytes);
    }
    (void)in_sizes; (void)n_in;
}

// round 5
// speedup vs baseline: 1.9906x; 1.9906x over previous
#include <cuda_runtime.h>
#include <cstdint>

#define BATCH  64
#define HID    1024
#define VOCAB  4096
#define SEQ    256
#define NBLK   128
#define NTHR   256

// ---------------------------------------------------------------------------
// Global scratch (static device allocations are allowed)
// ---------------------------------------------------------------------------
__device__ float g_H[(SEQ + 1) * BATCH * HID];   // hidden states, g_H[0]=H0
__device__ float g_z[BATCH * HID];               // z gate
__device__ float g_P[BATCH * HID];               // r * H
__device__ unsigned g_bar_count = 0;
__device__ volatile unsigned g_bar_gen = 0;

// ---------------------------------------------------------------------------
// helpers
// ---------------------------------------------------------------------------
__device__ __forceinline__ float tf32r(float x) {
    unsigned u;
    asm("cvt.rna.tf32.f32 %0, %1;" : "=r"(u) : "f"(x));
    return __uint_as_float(u);
}

__device__ __forceinline__ void mma8(float (&c)[4], const float (&a)[4], float b0, float b1) {
    unsigned a0 = __float_as_uint(a[0]), a1 = __float_as_uint(a[1]);
    unsigned a2 = __float_as_uint(a[2]), a3 = __float_as_uint(a[3]);
    unsigned B0 = __float_as_uint(b0),  B1 = __float_as_uint(b1);
    asm volatile(
        "mma.sync.aligned.m16n8k8.row.col.f32.tf32.tf32.f32 "
        "{%0,%1,%2,%3}, {%4,%5,%6,%7}, {%8,%9}, {%0,%1,%2,%3};\n"
        : "+f"(c[0]), "+f"(c[1]), "+f"(c[2]), "+f"(c[3])
        : "r"(a0), "r"(a1), "r"(a2), "r"(a3), "r"(B0), "r"(B1));
}

__device__ __forceinline__ float sigmoidf_(float x) { return 1.f / (1.f + __expf(-x)); }

// Software grid barrier. Safe: grid=NBLK blocks, 1 block/SM (smem), all resident.
__device__ __forceinline__ void gridbar() {
    __threadfence();          // publish this thread's prior writes (all threads)
    __syncthreads();
    if (threadIdx.x == 0) {
        unsigned gen = g_bar_gen;
        if (atomicAdd(&g_bar_count, 1u) == NBLK - 1) {
            g_bar_count = 0;
            __threadfence();
            g_bar_gen = gen + 1;
        } else {
            while (g_bar_gen == gen) { }
        }
        __threadfence();
    }
    __syncthreads();
}

// ---------------------------------------------------------------------------
// Persistent recurrence kernel.
//   Phase A: blocks 0..63  -> z cols [16b,16b+16); blocks 64..127 -> r cols.
//   Phase B: all blocks    -> h cols [8b,8b+8) + H update.
//   Warp layout per phase: wid = mt*2 + kh ; mt in [0,4) rows [16mt,16mt+16),
//   kh = K-half within each 256-wide chunk. Cross-warp K-reduce via smem.
// ---------------------------------------------------------------------------
__global__ void __launch_bounds__(NTHR, 1)
gru_persist(const int* __restrict__ X,
            const float* __restrict__ Wz, const float* __restrict__ bz,
            const float* __restrict__ Wr, const float* __restrict__ br,
            const float* __restrict__ Wh, const float* __restrict__ bh)
{
    extern __shared__ float sm[];
    float* sWa  = sm;                 // 16384 floats: phase-A weights (b-frag packed)
    float* sWh  = sWa + 16384;        //  8192 floats: phase-B weights
    float* sA   = sWh + 8192;         // 16640 floats: A chunk, [64][260]
    float* sRed = sA + 16640;         //  1024 floats: K-half reduction
    float* sX   = sRed + 1024;        //    64 floats: token ids (bit-cast)

    const int tid  = threadIdx.x;
    const int bid  = blockIdx.x;
    const int lane = tid & 31;
    const int wid  = tid >> 5;
    const int mt   = wid >> 1;        // m-tile 0..3
    const int kh   = wid & 1;         // K-half 0..1
    const int gid  = lane >> 2;
    const int tg   = lane & 3;

    const bool isZ = (bid < 64);
    const int  n0A = (bid & 63) * 16;
    const int  n0B = bid * 8;
    const float* WA = isZ ? Wz : Wr;
    const float* bA = isZ ? bz : br;

    // ---- pack recurrent weights into smem b-fragment layout (tf32-rounded) ----
    // sWa[e]: e = ((k8*2 + nt)*32 + lane)*2 + reg ; value = W[k8*8 + reg*4 + tg][n0A + nt*8 + gid]
    for (int e = tid; e < 16384; e += NTHR) {
        int reg = e & 1, ln = (e >> 1) & 31, nt = (e >> 6) & 1, k8 = e >> 7;
        int k   = k8 * 8 + reg * 4 + (ln & 3);
        int col = n0A + nt * 8 + (ln >> 2);
        sWa[e] = tf32r(WA[(size_t)(VOCAB + k) * HID + col]);
    }
    for (int e = tid; e < 8192; e += NTHR) {
        int reg = e & 1, ln = (e >> 1) & 31, k8 = e >> 6;
        int k   = k8 * 8 + reg * 4 + (ln & 3);
        int col = n0B + (ln >> 2);
        sWh[e] = tf32r(Wh[(size_t)(VOCAB + k) * HID + col]);
    }

    // ---- zero H0 (128 blocks x 256 thr x 2 floats = 65536) ----
    {
        int base = bid * 512 + tid * 2;
        g_H[base] = 0.f; g_H[base + 1] = 0.f;
    }
    gridbar();

    for (int t = 0; t < SEQ; ++t) {
        const float* Hc = g_H + (size_t)t * (BATCH * HID);
        float*       Hn = g_H + (size_t)(t + 1) * (BATCH * HID);

        if (tid < BATCH) sX[tid] = __int_as_float(X[tid * SEQ + t]);

        // ================= Phase A: z / r gates =================
        float acc[2][4];
#pragma unroll
        for (int nt = 0; nt < 2; ++nt)
#pragma unroll
            for (int j = 0; j < 4; ++j) acc[nt][j] = 0.f;

#pragma unroll
        for (int ch = 0; ch < 4; ++ch) {
            __syncthreads();
            // stage H chunk [64][256] -> sA (tf32-rounded)
#pragma unroll
            for (int it = 0; it < 16; ++it) {
                int flat = it * NTHR + tid;
                int row  = flat >> 6;
                int kw   = flat & 63;
                float4 v = __ldcg(reinterpret_cast<const float4*>(
                    Hc + (size_t)row * HID + ch * 256 + kw * 4));
                v.x = tf32r(v.x); v.y = tf32r(v.y); v.z = tf32r(v.z); v.w = tf32r(v.w);
                *reinterpret_cast<float4*>(sA + row * 260 + kw * 4) = v;
            }
            __syncthreads();

            const float* aBase = sA + (mt * 16 + gid) * 260;
#pragma unroll
            for (int k8c = 0; k8c < 16; ++k8c) {
                int kb = (kh * 16 + k8c) * 8;
                float a[4];
                a[0] = aBase[kb + tg];
                a[1] = aBase[8 * 260 + kb + tg];
                a[2] = aBase[kb + 4 + tg];
                a[3] = aBase[8 * 260 + kb + 4 + tg];
                int k8g = ch * 32 + kh * 16 + k8c;
#pragma unroll
                for (int nt = 0; nt < 2; ++nt) {
                    float2 b = *reinterpret_cast<const float2*>(
                        sWa + ((k8g * 2 + nt) * 32 + lane) * 2);
                    mma8(acc[nt], a, b.x, b.y);
                }
            }
        }
        __syncthreads();
        if (kh == 1) {
#pragma unroll
            for (int nt = 0; nt < 2; ++nt)
                *reinterpret_cast<float4*>(sRed + ((mt * 2 + nt) * 32 + lane) * 4) =
                    make_float4(acc[nt][0], acc[nt][1], acc[nt][2], acc[nt][3]);
        }
        __syncthreads();
        if (kh == 0) {
#pragma unroll
            for (int nt = 0; nt < 2; ++nt) {
                float4 r4 = *reinterpret_cast<const float4*>(
                    sRed + ((mt * 2 + nt) * 32 + lane) * 4);
                float red[4] = {r4.x, r4.y, r4.z, r4.w};
#pragma unroll
                for (int j = 0; j < 4; ++j) {
                    int row = mt * 16 + gid + (j >> 1) * 8;
                    int n   = n0A + nt * 8 + tg * 2 + (j & 1);
                    int x   = __float_as_int(sX[row]);
                    float pre = acc[nt][j] + red[j] + WA[(size_t)x * HID + n] + bA[n];
                    float s   = sigmoidf_(pre);
                    int idx   = row * HID + n;
                    if (isZ) g_z[idx] = s;
                    else     g_P[idx] = s * __ldcg(Hc + idx);
                }
            }
        }
        gridbar();

        // ================= Phase B: h gate + H update =================
        float acch[4] = {0.f, 0.f, 0.f, 0.f};
#pragma unroll
        for (int ch = 0; ch < 4; ++ch) {
            __syncthreads();
#pragma unroll
            for (int it = 0; it < 16; ++it) {
                int flat = it * NTHR + tid;
                int row  = flat >> 6;
                int kw   = flat & 63;
                float4 v = __ldcg(reinterpret_cast<const float4*>(
                    g_P + (size_t)row * HID + ch * 256 + kw * 4));
                v.x = tf32r(v.x); v.y = tf32r(v.y); v.z = tf32r(v.z); v.w = tf32r(v.w);
                *reinterpret_cast<float4*>(sA + row * 260 + kw * 4) = v;
            }
            __syncthreads();

            const float* aBase = sA + (mt * 16 + gid) * 260;
#pragma unroll
            for (int k8c = 0; k8c < 16; ++k8c) {
                int kb = (kh * 16 + k8c) * 8;
                float a[4];
                a[0] = aBase[kb + tg];
                a[1] = aBase[8 * 260 + kb + tg];
                a[2] = aBase[kb + 4 + tg];
                a[3] = aBase[8 * 260 + kb + 4 + tg];
                int k8g = ch * 32 + kh * 16 + k8c;
                float2 b = *reinterpret_cast<const float2*>(sWh + (k8g * 32 + lane) * 2);
                mma8(acch, a, b.x, b.y);
            }
        }
        __syncthreads();
        if (kh == 1)
            *reinterpret_cast<float4*>(sRed + (mt * 32 + lane) * 4) =
                make_float4(acch[0], acch[1], acch[2], acch[3]);
        __syncthreads();
        if (kh == 0) {
            float4 r4 = *reinterpret_cast<const float4*>(sRed + (mt * 32 + lane) * 4);
            float red[4] = {r4.x, r4.y, r4.z, r4.w};
#pragma unroll
            for (int j = 0; j < 4; ++j) {
                int row = mt * 16 + gid + (j >> 1) * 8;
                int n   = n0B + tg * 2 + (j & 1);
                int x   = __float_as_int(sX[row]);
                float pre = acch[j] + red[j] + Wh[(size_t)x * HID + n] + bh[n];
                float h   = tanhf(pre);
                int idx   = row * HID + n;
                float z   = __ldcg(g_z + idx);
                float hc  = __ldcg(Hc + idx);
                Hn[idx] = z * h + (1.f - z) * hc;
            }
        }
        gridbar();
    }
}

// ---------------------------------------------------------------------------
// Output GEMM: Y = H_all[16384 x 1024] @ Wo[1024 x 4096] + bo  (unchanged R4)
// ---------------------------------------------------------------------------
template<int NI>
__device__ __forceinline__ void gemm_core_out(
    const float* __restrict__ A,
    const float* __restrict__ B0,
    const float* __restrict__ B1,
    int ldb, float (&acc)[2][NI][4], float* As, float* Bs)
{
    constexpr int BN = NI * 16, BSTR = BN + 8;
    const int tid = threadIdx.x, lane = tid & 31, w = tid >> 5;
    const int wm = w >> 1, wn = w & 1, gid = lane >> 2, tg = lane & 3;

#pragma unroll
    for (int mi = 0; mi < 2; ++mi)
#pragma unroll
        for (int ni = 0; ni < NI; ++ni)
#pragma unroll
            for (int e = 0; e < 4; ++e) acc[mi][ni][e] = 0.f;

    float4 ra[4]; float4 rb[NI];
#pragma unroll
    for (int j = 0; j < 4; ++j) {
        int i = tid + j * 128, row = i >> 3, kq = i & 7;
        ra[j] = *reinterpret_cast<const float4*>(A + (size_t)row * HID + kq * 4);
    }
#pragma unroll
    for (int j = 0; j < NI; ++j) {
        int i = tid + j * 128, row = i / (BN / 4), nq = i % (BN / 4), c4 = nq * 4;
        const float* src = (c4 < NI * 8) ? (B0 + (size_t)row * ldb + c4)
                                         : (B1 + (size_t)row * ldb + (c4 - NI * 8));
        rb[j] = *reinterpret_cast<const float4*>(src);
    }

    for (int kk = 0; kk < HID; kk += 32) {
#pragma unroll
        for (int j = 0; j < 4; ++j) {
            int i = tid + j * 128, row = i >> 3, kq = i & 7;
            float4 v; v.x = tf32r(ra[j].x); v.y = tf32r(ra[j].y);
            v.z = tf32r(ra[j].z); v.w = tf32r(ra[j].w);
            *reinterpret_cast<float4*>(As + row * 36 + kq * 4) = v;
        }
#pragma unroll
        for (int j = 0; j < NI; ++j) {
            int i = tid + j * 128, row = i / (BN / 4), nq = i % (BN / 4);
            float4 v; v.x = tf32r(rb[j].x); v.y = tf32r(rb[j].y);
            v.z = tf32r(rb[j].z); v.w = tf32r(rb[j].w);
            *reinterpret_cast<float4*>(Bs + row * BSTR + nq * 4) = v;
        }
        __syncthreads();
        if (kk + 32 < HID) {
#pragma unroll
            for (int j = 0; j < 4; ++j) {
                int i = tid + j * 128, row = i >> 3, kq = i & 7;
                ra[j] = *reinterpret_cast<const float4*>(A + (size_t)row * HID + kk + 32 + kq * 4);
            }
#pragma unroll
            for (int j = 0; j < NI; ++j) {
                int i = tid + j * 128, row = i / (BN / 4), nq = i % (BN / 4), c4 = nq * 4;
                const float* src = (c4 < NI * 8)
                    ? (B0 + (size_t)(kk + 32 + row) * ldb + c4)
                    : (B1 + (size_t)(kk + 32 + row) * ldb + (c4 - NI * 8));
                rb[j] = *reinterpret_cast<const float4*>(src);
            }
        }
#pragma unroll
        for (int k8 = 0; k8 < 4; ++k8) {
            int kb = k8 * 8;
            float a[2][4];
#pragma unroll
            for (int mi = 0; mi < 2; ++mi) {
                int rb0 = wm * 32 + mi * 16;
                a[mi][0] = As[(rb0 + gid) * 36 + kb + tg];
                a[mi][1] = As[(rb0 + 8 + gid) * 36 + kb + tg];
                a[mi][2] = As[(rb0 + gid) * 36 + kb + 4 + tg];
                a[mi][3] = As[(rb0 + 8 + gid) * 36 + kb + 4 + tg];
            }
#pragma unroll
            for (int ni = 0; ni < NI; ++ni) {
                int col = wn * (NI * 8) + ni * 8 + gid;
                float b0 = Bs[(kb + tg) * BSTR + col];
                float b1 = Bs[(kb + 4 + tg) * BSTR + col];
#pragma unroll
                for (int mi = 0; mi < 2; ++mi) mma8(acc[mi][ni], a[mi], b0, b1);
            }
        }
        __syncthreads();
    }
}

__global__ void __launch_bounds__(128)
gru_out(const float* __restrict__ Wo, const float* __restrict__ bo,
        float* __restrict__ out)
{
    __shared__ float As[64 * 36];
    __shared__ float Bs[32 * 72];

    const int n0 = blockIdx.x * 64;
    const int m0 = blockIdx.y * 64;
    const float* A  = g_H + (size_t)(BATCH * HID) + (size_t)m0 * HID;
    const float* B0 = Wo + n0;
    const float* B1 = Wo + n0 + 32;

    float acc[2][4][4];
    gemm_core_out<4>(A, B0, B1, VOCAB, acc, As, Bs);

    const int lane = threadIdx.x & 31, w = threadIdx.x >> 5;
    const int wm = w >> 1, wn = w & 1, gid = lane >> 2, tg = lane & 3;

#pragma unroll
    for (int mi = 0; mi < 2; ++mi)
#pragma unroll
        for (int half = 0; half < 2; ++half) {
            int row = m0 + wm * 32 + mi * 16 + half * 8 + gid;
#pragma unroll
            for (int ni = 0; ni < 4; ++ni)
#pragma unroll
                for (int e = 0; e < 2; ++e) {
                    int n = n0 + wn * 32 + ni * 8 + tg * 2 + e;
                    out[(size_t)row * VOCAB + n] = acc[mi][ni][half * 2 + e] + bo[n];
                }
        }
}

__global__ void gru_copy_hfinal(float* __restrict__ dst) {
    int i = blockIdx.x * blockDim.x + threadIdx.x;
    if (i < BATCH * HID) dst[i] = g_H[(size_t)SEQ * (BATCH * HID) + i];
}

// ---------------------------------------------------------------------------
extern "C" void kernel_launch(void* const* d_in, const int* in_sizes, int n_in,
                              void* d_out, int out_size)
{
    const int*   X  = (const int*)  d_in[0];
    const float* Wz = (const float*)d_in[1];
    const float* bz = (const float*)d_in[2];
    const float* Wr = (const float*)d_in[3];
    const float* br = (const float*)d_in[4];
    const float* Wh = (const float*)d_in[5];
    const float* bh = (const float*)d_in[6];
    const float* Wo = (const float*)d_in[7];
    const float* bo = (const float*)d_in[8];
    float* out = (float*)d_out;

    const int smemBytes = (16384 + 8192 + 16640 + 1024 + 64) * 4;  // 169216 B
    cudaFuncSetAttribute(gru_persist, cudaFuncAttributeMaxDynamicSharedMemorySize, smemBytes);

    gru_persist<<<NBLK, NTHR, smemBytes>>>(X, Wz, bz, Wr, br, Wh, bh);

    gru_out<<<dim3(VOCAB / 64, (SEQ * BATCH) / 64), 128>>>(Wo, bo, out);

    const long long ybytes = (long long)SEQ * BATCH * VOCAB;
    if ((long long)out_size >= ybytes + (long long)BATCH * HID) {
        gru_copy_hfinal<<<64, 1024>>>(out + ybytes);
    }
    (void)in_sizes; (void)n_in;
}